// round 6
// baseline (speedup 1.0000x reference)
#include <cuda_runtime.h>

#define WIN   3072
#define HOP   192
#define NB    8
#define NT    1000
#define NF    128
#define NOISE_LEN ((NT-1)*HOP)   /* 191808 */
#define HALF  (WIN/2)            /* 1536 */
#define NTHREADS 256

#define PHY(i) ((i) + ((i)>>5))
#define SBUF (WIN + (WIN>>5))    /* 3168 */

__device__ float2 g_tw[WIN];      // w3072^j = exp(-2*pi*i*j/3072)
__device__ float  g_hann[WIN];
__device__ float  g_scratch[NB*NT*WIN];   // windowed out_frames, ~98 MB

// ---------------------------------------------------------------- complex ops
__device__ __forceinline__ float2 cadd(float2 a, float2 b){ return make_float2(a.x+b.x, a.y+b.y); }
__device__ __forceinline__ float2 csub(float2 a, float2 b){ return make_float2(a.x-b.x, a.y-b.y); }
__device__ __forceinline__ float2 cmul(float2 a, float2 b){
    return make_float2(a.x*b.x - a.y*b.y, a.x*b.y + a.y*b.x);
}

// forward DFT-4 (e^{-2pi i jk/4})
__device__ __forceinline__ void dft4(float2 &a0, float2 &a1, float2 &a2, float2 &a3){
    float2 t0 = cadd(a0,a2), t1 = csub(a0,a2);
    float2 t2 = cadd(a1,a3), t3 = csub(a1,a3);
    a0 = cadd(t0,t2);
    a2 = csub(t0,t2);
    a1 = make_float2(t1.x + t3.y, t1.y - t3.x);  // t1 - i*t3
    a3 = make_float2(t1.x - t3.y, t1.y + t3.x);  // t1 + i*t3
}

// forward DFT-3
__device__ __forceinline__ void dft3(float2 &a, float2 &b, float2 &c){
    float2 s = cadd(b,c);
    float2 d = csub(b,c);
    float2 t = make_float2(a.x - 0.5f*s.x, a.y - 0.5f*s.y);
    float ux = 0.8660254037844386f*d.x, uy = 0.8660254037844386f*d.y;
    float2 y0 = cadd(a,s);
    b = make_float2(t.x + uy, t.y - ux);  // t - i*u
    c = make_float2(t.x - uy, t.y + ux);  // t + i*u
    a = y0;
}

// DFT-12, input v[j] with j = r + 4c. After: X[k3 + 3*k1] at v[k1 + 4*k3].
__device__ __forceinline__ void dft12(float2 *v){
    dft3(v[0], v[4], v[8]);
    dft3(v[1], v[5], v[9]);
    dft3(v[2], v[6], v[10]);
    dft3(v[3], v[7], v[11]);
    const float H3 = 0.8660254037844386f;
    v[5]  = cmul(v[5],  make_float2( H3,  -0.5f));   // w12^1
    v[6]  = cmul(v[6],  make_float2( 0.5f, -H3));    // w12^2
    v[7]  = make_float2(v[7].y, -v[7].x);            // w12^3 = -i
    v[9]  = cmul(v[9],  make_float2( 0.5f, -H3));    // w12^2
    v[10] = cmul(v[10], make_float2(-0.5f, -H3));    // w12^4
    v[11] = make_float2(-v[11].x, -v[11].y);         // w12^6 = -1
    dft4(v[0], v[1], v[2],  v[3]);
    dft4(v[4], v[5], v[6],  v[7]);
    dft4(v[8], v[9], v[10], v[11]);
}

// DFT-16, input v[j] with j = r + 4c. After: X[k4 + 4*k1] at v[k1 + 4*k4].
__device__ __forceinline__ void dft16(float2 *v){
    dft4(v[0], v[4], v[8],  v[12]);
    dft4(v[1], v[5], v[9],  v[13]);
    dft4(v[2], v[6], v[10], v[14]);
    dft4(v[3], v[7], v[11], v[15]);
    const float C1 = 0.9238795325112867f;
    const float S1 = 0.3826834323650898f;
    const float R2 = 0.7071067811865476f;
    v[5]  = cmul(v[5],  make_float2( C1, -S1));   // w16^1
    v[6]  = cmul(v[6],  make_float2( R2, -R2));   // w16^2
    v[7]  = cmul(v[7],  make_float2( S1, -C1));   // w16^3
    v[9]  = cmul(v[9],  make_float2( R2, -R2));   // w16^2
    v[10] = make_float2(v[10].y, -v[10].x);       // w16^4 = -i
    v[11] = cmul(v[11], make_float2(-R2, -R2));   // w16^6
    v[13] = cmul(v[13], make_float2( S1, -C1));   // w16^3
    v[14] = cmul(v[14], make_float2(-R2, -R2));   // w16^6
    v[15] = cmul(v[15], make_float2(-C1,  S1));   // w16^9
    dft4(v[0], v[1], v[2],  v[3]);
    dft4(v[4], v[5], v[6],  v[7]);
    dft4(v[8], v[9], v[10], v[11]);
    dft4(v[12],v[13],v[14], v[15]);
}

// In-place (register-staged) 3072-point complex FFT over shared float2.
// Stages: radix-12 (s=1), radix-16 (s=12), radix-16 (s=192). Natural order out.
// Twiddles generated iteratively from one coalesced base load per stage
// (avoids the strided g_tw[p*k] gathers and their L1 wavefront blowup).
__device__ void fft3072(float2 *Z, int tid){
    float2 v[16];

    // ---- stage 1: radix-12, 256 butterflies, one per thread
    {
        int p = tid;
        #pragma unroll
        for (int i = 0; i < 12; i++) v[i] = Z[PHY(p + 256*i)];
        float2 w1 = g_tw[p];        // w3072^p  (coalesced)
        __syncthreads();
        dft12(v);
        Z[PHY(12*p)] = v[0];
        float2 wc = w1;             // wc = w3072^{p*k}
        #pragma unroll
        for (int k = 1; k < 12; k++){
            float2 X = cmul(v[(k/3) + 4*(k%3)], wc);
            Z[PHY(12*p + k)] = X;
            if (k < 11) wc = cmul(wc, w1);
        }
        __syncthreads();
    }

    // ---- stage 2: radix-16, s=12, 192 butterflies (tid = 12*p + q)
    {
        bool act = tid < 192;
        int q = tid % 12, p = tid / 12;
        float2 ws;
        if (act){
            #pragma unroll
            for (int i = 0; i < 16; i++) v[i] = Z[PHY(tid + 192*i)];
            ws = g_tw[12*p];        // w256^p (few lines per warp)
        }
        __syncthreads();
        if (act){
            dft16(v);
            Z[PHY(q + 192*p)] = v[0];
            float2 wc = ws;         // wc = w256^{p*k}
            #pragma unroll
            for (int k = 1; k < 16; k++){
                float2 X = cmul(v[(k>>2) + 4*(k&3)], wc);
                Z[PHY(q + 192*p + 12*k)] = X;
                if (k < 15) wc = cmul(wc, ws);
            }
        }
        __syncthreads();
    }

    // ---- stage 3: radix-16, s=192, no twiddle
    {
        bool act = tid < 192;
        if (act){
            #pragma unroll
            for (int i = 0; i < 16; i++) v[i] = Z[PHY(tid + 192*i)];
        }
        __syncthreads();
        if (act){
            dft16(v);
            #pragma unroll
            for (int k = 0; k < 16; k++){
                float2 X = v[(k>>2) + 4*(k&3)];
                Z[PHY(tid + 192*k)] = X;
            }
        }
        __syncthreads();
    }
}

// ---------------------------------------------------------------- kernels
__global__ void init_tables(){
    int j = blockIdx.x*blockDim.x + threadIdx.x;
    if (j < WIN){
        float s, c;
        sincospif(-2.0f * (float)j / (float)WIN, &s, &c);
        g_tw[j] = make_float2(c, s);
        float sh = sinpif((float)j / (float)(WIN-1));
        g_hann[j] = sh * sh;   // 0.5 - 0.5*cos(2*pi*j/(N-1))
    }
}

// One block = one PAIR of frames (2t, 2t+1) packed as z = x + i*y.
__global__ void __launch_bounds__(NTHREADS, 4)
synth_kernel(const float* __restrict__ fb, const float* __restrict__ noise){
    __shared__ float2 Z[SBUF];
    __shared__ float gsx[NF];
    __shared__ float gsy[NF];

    int tp  = blockIdx.x;          // 0..499
    int b   = blockIdx.y;
    int tid = threadIdx.x;
    int t0  = 2*tp;

    // filter gains for frames t0, t0+1
    if (tid < NF){
        float2 g2 = *(const float2*)&fb[(b*NF + tid)*NT + t0];
        gsx[tid] = g2.x;
        gsy[tid] = g2.y;
    }

    // load both frames vectorized: Z[n] = x[n] + i*y[n]
    // base = 384*(tp-4): 4-aligned; NOISE_LEN % 4 == 0 so each float4 group is
    // entirely in-range or entirely out-of-range.
    int base = t0*HOP - HALF;
    const float* nb = noise + b*NOISE_LEN;
    #pragma unroll
    for (int it = 0; it < WIN/(4*NTHREADS); it++){
        int n  = 4*(tid + NTHREADS*it);
        int i0 = base + n;
        int i1 = i0 + HOP;
        float4 x4 = (i0 >= 0 && i0 + 3 < NOISE_LEN) ? *(const float4*)&nb[i0]
                                                    : make_float4(0.f,0.f,0.f,0.f);
        float4 y4 = (i1 >= 0 && i1 + 3 < NOISE_LEN) ? *(const float4*)&nb[i1]
                                                    : make_float4(0.f,0.f,0.f,0.f);
        Z[PHY(n+0)] = make_float2(x4.x, y4.x);
        Z[PHY(n+1)] = make_float2(x4.y, y4.y);
        Z[PHY(n+2)] = make_float2(x4.z, y4.z);
        Z[PHY(n+3)] = make_float2(x4.w, y4.w);
    }
    __syncthreads();

    // forward FFT of packed pair
    fft3072(Z, tid);

    // Spectral separation + real filter + conjugate (inverse-via-forward).
    //   X[k] = (Z[k] + conj(Z[N-k]))/2,  Y[k] = -i*(Z[k] - conj(Z[N-k]))/2
    //   W[k]   = Hx*X + i*Hy*Y ;  W[N-k] = Hx*conj(X) + i*Hy*conj(Y)
    // store conj(W) so a forward FFT realizes the inverse.
    for (int k = tid + 1; k < HALF; k += NTHREADS){
        float2 A = Z[PHY(k)];
        float2 B = Z[PHY(WIN - k)];
        float Xx = 0.5f*(A.x + B.x), Xy = 0.5f*(A.y - B.y);
        float Yx = 0.5f*(A.y + B.y), Yy = -0.5f*(A.x - B.x);
        int band = (k - 1)/12;
        float hx = gsx[band], hy = gsy[band];
        float Wx  = hx*Xx - hy*Yy;
        float Wy  = hx*Xy + hy*Yx;
        float Vx  = hx*Xx + hy*Yy;
        float Vy  = -hx*Xy + hy*Yx;
        Z[PHY(k)]       = make_float2(Wx, -Wy);
        Z[PHY(WIN - k)] = make_float2(Vx, -Vy);
    }
    if (tid == 0){
        Z[PHY(0)] = make_float2(0.0f, 0.0f);      // H[0] = 0
        float2 A = Z[PHY(HALF)];                  // Nyquist (real X, real Y)
        Z[PHY(HALF)] = make_float2(gsx[NF-1]*A.x, -gsy[NF-1]*A.y);
    }
    __syncthreads();

    // forward FFT realizes inverse:  ifft(W) = conj(fft(conj(W)))/N
    fft3072(Z, tid);

    // window + store both frames vectorized
    const float inv = 1.0f/(float)WIN;
    float* scx = g_scratch + (b*NT + t0)*WIN;
    float* scy = scx + WIN;
    #pragma unroll
    for (int it = 0; it < WIN/(4*NTHREADS); it++){
        int n = 4*(tid + NTHREADS*it);
        float4 h4 = *(const float4*)&g_hann[n];
        float2 u0 = Z[PHY(n+0)], u1 = Z[PHY(n+1)], u2 = Z[PHY(n+2)], u3 = Z[PHY(n+3)];
        float4 xo = make_float4( u0.x*inv*h4.x,  u1.x*inv*h4.y,  u2.x*inv*h4.z,  u3.x*inv*h4.w);
        float4 yo = make_float4(-u0.y*inv*h4.x, -u1.y*inv*h4.y, -u2.y*inv*h4.z, -u3.y*inv*h4.w);
        *(float4*)&scx[n] = xo;
        *(float4*)&scy[n] = yo;
    }
}

// 4 consecutive outputs per thread; interior frames contribute aligned float4.
__global__ void ola_kernel(float* __restrict__ out){
    const int GP = NOISE_LEN/4;            // 47952 groups per batch
    int gid = blockIdx.x*blockDim.x + threadIdx.x;
    if (gid >= NB*GP) return;
    int b = gid / GP;
    int g = gid - b*GP;
    int s = 4*g + HALF;                    // s % 4 == 0
    const float* base = g_scratch + b*NT*WIN;

    int tl0 = (s     >= 2880) ? (s     - 2880)/HOP : 0;   // t_lo for element 0
    int tl3 = (s + 3 >= 2880) ? (s + 3 - 2880)/HOP : 0;   // t_lo for element 3
    int th0 = s/HOP;       if (th0 > NT-1) th0 = NT-1;    // t_hi for element 0
    int th3 = (s + 3)/HOP; if (th3 > NT-1) th3 = NT-1;    // t_hi for element 3

    float4 acc = make_float4(0.f, 0.f, 0.f, 0.f);
    // frames valid for all 4 elements: aligned float4 loads
    for (int tt = tl3; tt <= th0; tt++){
        float4 vv = *(const float4*)&base[tt*WIN + (s - HOP*tt)];
        acc.x += vv.x; acc.y += vv.y; acc.z += vv.z; acc.w += vv.w;
    }
    // low-boundary frame(s): valid only for the leading elements (o+j <= 3071)
    for (int tt = tl0; tt < tl3; tt++){
        int o0 = s - HOP*tt;
        if (o0+0 <= WIN-1) acc.x += base[tt*WIN + o0+0];
        if (o0+1 <= WIN-1) acc.y += base[tt*WIN + o0+1];
        if (o0+2 <= WIN-1) acc.z += base[tt*WIN + o0+2];
        if (o0+3 <= WIN-1) acc.w += base[tt*WIN + o0+3];
    }
    // high-boundary frame(s): valid only for the trailing elements (o+j >= 0)
    for (int tt = th0+1; tt <= th3; tt++){
        int o0 = s - HOP*tt;
        if (o0+0 >= 0) acc.x += base[tt*WIN + o0+0];
        if (o0+1 >= 0) acc.y += base[tt*WIN + o0+1];
        if (o0+2 >= 0) acc.z += base[tt*WIN + o0+2];
        if (o0+3 >= 0) acc.w += base[tt*WIN + o0+3];
    }
    *(float4*)&out[b*NOISE_LEN + 4*g] = acc;
}

// ---------------------------------------------------------------- launch
extern "C" void kernel_launch(void* const* d_in, const int* in_sizes, int n_in,
                              void* d_out, int out_size){
    const float* fb    = (const float*)d_in[0];
    const float* noise = (const float*)d_in[1];
    if (n_in >= 2 && in_sizes[0] == NB*NOISE_LEN && in_sizes[1] == NB*NF*NT){
        const float* tmp = fb; fb = noise; noise = tmp;
    }
    float* out = (float*)d_out;

    init_tables<<<(WIN + 255)/256, 256>>>();
    dim3 grid(NT/2, NB);
    synth_kernel<<<grid, NTHREADS>>>(fb, noise);
    int n_groups = NB*(NOISE_LEN/4);
    ola_kernel<<<(n_groups + 255)/256, 256>>>(out);
}

// round 7
// speedup vs baseline: 1.3072x; 1.3072x over previous
#include <cuda_runtime.h>

#define WIN   3072
#define HOP   192
#define NB    8
#define NT    1000
#define NF    128
#define NOISE_LEN ((NT-1)*HOP)   /* 191808 */
#define HALF  (WIN/2)            /* 1536 */
#define NTHREADS 256

#define PHY(i) ((i) + ((i)>>5))
#define SBUF (WIN + (WIN>>5))    /* 3168 */
#define SMEM_BYTES (2*SBUF*(int)sizeof(float2))   /* 50688 */

__device__ float2 g_tw[WIN];      // w3072^j = exp(-2*pi*i*j/3072)
__device__ float  g_hann[WIN];
__device__ float  g_scratch[NB*NT*WIN];   // windowed out_frames, ~98 MB

// ---------------------------------------------------------------- complex ops
__device__ __forceinline__ float2 cadd(float2 a, float2 b){ return make_float2(a.x+b.x, a.y+b.y); }
__device__ __forceinline__ float2 csub(float2 a, float2 b){ return make_float2(a.x-b.x, a.y-b.y); }
__device__ __forceinline__ float2 cmul(float2 a, float2 b){
    return make_float2(a.x*b.x - a.y*b.y, a.x*b.y + a.y*b.x);
}

// forward DFT-4 (e^{-2pi i jk/4})
__device__ __forceinline__ void dft4(float2 &a0, float2 &a1, float2 &a2, float2 &a3){
    float2 t0 = cadd(a0,a2), t1 = csub(a0,a2);
    float2 t2 = cadd(a1,a3), t3 = csub(a1,a3);
    a0 = cadd(t0,t2);
    a2 = csub(t0,t2);
    a1 = make_float2(t1.x + t3.y, t1.y - t3.x);  // t1 - i*t3
    a3 = make_float2(t1.x - t3.y, t1.y + t3.x);  // t1 + i*t3
}

// forward DFT-3
__device__ __forceinline__ void dft3(float2 &a, float2 &b, float2 &c){
    float2 s = cadd(b,c);
    float2 d = csub(b,c);
    float2 t = make_float2(a.x - 0.5f*s.x, a.y - 0.5f*s.y);
    float ux = 0.8660254037844386f*d.x, uy = 0.8660254037844386f*d.y;
    float2 y0 = cadd(a,s);
    b = make_float2(t.x + uy, t.y - ux);  // t - i*u
    c = make_float2(t.x - uy, t.y + ux);  // t + i*u
    a = y0;
}

// DFT-12, input v[j] with j = r + 4c. After: X[k3 + 3*k1] at v[k1 + 4*k3].
__device__ __forceinline__ void dft12(float2 *v){
    dft3(v[0], v[4], v[8]);
    dft3(v[1], v[5], v[9]);
    dft3(v[2], v[6], v[10]);
    dft3(v[3], v[7], v[11]);
    const float H3 = 0.8660254037844386f;
    v[5]  = cmul(v[5],  make_float2( H3,  -0.5f));   // w12^1
    v[6]  = cmul(v[6],  make_float2( 0.5f, -H3));    // w12^2
    v[7]  = make_float2(v[7].y, -v[7].x);            // w12^3 = -i
    v[9]  = cmul(v[9],  make_float2( 0.5f, -H3));    // w12^2
    v[10] = cmul(v[10], make_float2(-0.5f, -H3));    // w12^4
    v[11] = make_float2(-v[11].x, -v[11].y);         // w12^6 = -1
    dft4(v[0], v[1], v[2],  v[3]);
    dft4(v[4], v[5], v[6],  v[7]);
    dft4(v[8], v[9], v[10], v[11]);
}

// DFT-16, input v[j] with j = r + 4c. After: X[k4 + 4*k1] at v[k1 + 4*k4].
__device__ __forceinline__ void dft16(float2 *v){
    dft4(v[0], v[4], v[8],  v[12]);
    dft4(v[1], v[5], v[9],  v[13]);
    dft4(v[2], v[6], v[10], v[14]);
    dft4(v[3], v[7], v[11], v[15]);
    const float C1 = 0.9238795325112867f;
    const float S1 = 0.3826834323650898f;
    const float R2 = 0.7071067811865476f;
    v[5]  = cmul(v[5],  make_float2( C1, -S1));   // w16^1
    v[6]  = cmul(v[6],  make_float2( R2, -R2));   // w16^2
    v[7]  = cmul(v[7],  make_float2( S1, -C1));   // w16^3
    v[9]  = cmul(v[9],  make_float2( R2, -R2));   // w16^2
    v[10] = make_float2(v[10].y, -v[10].x);       // w16^4 = -i
    v[11] = cmul(v[11], make_float2(-R2, -R2));   // w16^6
    v[13] = cmul(v[13], make_float2( S1, -C1));   // w16^3
    v[14] = cmul(v[14], make_float2(-R2, -R2));   // w16^6
    v[15] = cmul(v[15], make_float2(-C1,  S1));   // w16^9
    dft4(v[0], v[1], v[2],  v[3]);
    dft4(v[4], v[5], v[6],  v[7]);
    dft4(v[8], v[9], v[10], v[11]);
    dft4(v[12],v[13],v[14], v[15]);
}

// Out-of-place ping-pong 3072-point complex FFT: A -> B (A clobbered as scratch).
// Each stage reads every src element exactly once and writes disjoint dst
// elements, so only ONE barrier per stage is needed (after the writes).
// Stages: radix-12 (s=1) A->B, radix-16 (s=12) B->A, radix-16 (s=192) A->B.
__device__ void fft3072_pp(float2 *A, float2 *B, int tid){
    float2 v[16];

    // ---- stage 1: radix-12, 256 butterflies, A -> B
    {
        int p = tid;
        #pragma unroll
        for (int i = 0; i < 12; i++) v[i] = A[PHY(p + 256*i)];
        dft12(v);
        #pragma unroll
        for (int k = 0; k < 12; k++){
            float2 X = v[(k/3) + 4*(k%3)];
            if (k) X = cmul(X, g_tw[p*k]);
            B[PHY(12*p + k)] = X;
        }
        __syncthreads();
    }

    // ---- stage 2: radix-16, s=12, 192 butterflies, B -> A (tid = 12*p + q)
    {
        if (tid < 192){
            int q = tid % 12, p = tid / 12;
            #pragma unroll
            for (int i = 0; i < 16; i++) v[i] = B[PHY(tid + 192*i)];
            dft16(v);
            #pragma unroll
            for (int k = 0; k < 16; k++){
                float2 X = v[(k>>2) + 4*(k&3)];
                if (k && p) X = cmul(X, g_tw[12*p*k]);   // w256^{pk}
                A[PHY(q + 192*p + 12*k)] = X;
            }
        }
        __syncthreads();
    }

    // ---- stage 3: radix-16, s=192, no twiddle, A -> B
    {
        if (tid < 192){
            #pragma unroll
            for (int i = 0; i < 16; i++) v[i] = A[PHY(tid + 192*i)];
            dft16(v);
            #pragma unroll
            for (int k = 0; k < 16; k++){
                float2 X = v[(k>>2) + 4*(k&3)];
                B[PHY(tid + 192*k)] = X;
            }
        }
        __syncthreads();
    }
}

// ---------------------------------------------------------------- kernels
__global__ void init_tables(){
    int j = blockIdx.x*blockDim.x + threadIdx.x;
    if (j < WIN){
        float s, c;
        sincospif(-2.0f * (float)j / (float)WIN, &s, &c);
        g_tw[j] = make_float2(c, s);
        float sh = sinpif((float)j / (float)(WIN-1));
        g_hann[j] = sh * sh;   // 0.5 - 0.5*cos(2*pi*j/(N-1))
    }
}

// One block = one PAIR of frames (2t, 2t+1) packed as z = x + i*y.
__global__ void __launch_bounds__(NTHREADS, 3)
synth_kernel(const float* __restrict__ fb, const float* __restrict__ noise){
    extern __shared__ float2 smem2[];
    float2* Za = smem2;          // buffer A
    float2* Zb = smem2 + SBUF;   // buffer B
    __shared__ float gsx[NF];
    __shared__ float gsy[NF];

    int tp  = blockIdx.x;          // 0..499
    int b   = blockIdx.y;
    int tid = threadIdx.x;
    int t0  = 2*tp;

    // filter gains for frames t0, t0+1
    if (tid < NF){
        float2 g2 = *(const float2*)&fb[(b*NF + tid)*NT + t0];
        gsx[tid] = g2.x;
        gsy[tid] = g2.y;
    }

    // load both frames vectorized into A: Za[n] = x[n] + i*y[n]
    int base = t0*HOP - HALF;
    const float* nb = noise + b*NOISE_LEN;
    #pragma unroll
    for (int it = 0; it < WIN/(4*NTHREADS); it++){
        int n  = 4*(tid + NTHREADS*it);
        int i0 = base + n;
        int i1 = i0 + HOP;
        float4 x4 = (i0 >= 0 && i0 + 3 < NOISE_LEN) ? *(const float4*)&nb[i0]
                                                    : make_float4(0.f,0.f,0.f,0.f);
        float4 y4 = (i1 >= 0 && i1 + 3 < NOISE_LEN) ? *(const float4*)&nb[i1]
                                                    : make_float4(0.f,0.f,0.f,0.f);
        Za[PHY(n+0)] = make_float2(x4.x, y4.x);
        Za[PHY(n+1)] = make_float2(x4.y, y4.y);
        Za[PHY(n+2)] = make_float2(x4.z, y4.z);
        Za[PHY(n+3)] = make_float2(x4.w, y4.w);
    }
    __syncthreads();

    // forward FFT of packed pair: A -> B
    fft3072_pp(Za, Zb, tid);

    // Spectral separation + real filter + conjugate, B -> A.
    // Each (k, WIN-k) pair is owned by exactly one thread: no internal hazard.
    for (int k = tid + 1; k < HALF; k += NTHREADS){
        float2 A = Zb[PHY(k)];
        float2 B = Zb[PHY(WIN - k)];
        float Xx = 0.5f*(A.x + B.x), Xy = 0.5f*(A.y - B.y);
        float Yx = 0.5f*(A.y + B.y), Yy = -0.5f*(A.x - B.x);
        int band = (k - 1)/12;
        float hx = gsx[band], hy = gsy[band];
        float Wx  = hx*Xx - hy*Yy;
        float Wy  = hx*Xy + hy*Yx;
        float Vx  = hx*Xx + hy*Yy;
        float Vy  = -hx*Xy + hy*Yx;
        Za[PHY(k)]       = make_float2(Wx, -Wy);
        Za[PHY(WIN - k)] = make_float2(Vx, -Vy);
    }
    if (tid == 0){
        Za[PHY(0)] = make_float2(0.0f, 0.0f);      // H[0] = 0
        float2 A = Zb[PHY(HALF)];                  // Nyquist (real X, real Y)
        Za[PHY(HALF)] = make_float2(gsx[NF-1]*A.x, -gsy[NF-1]*A.y);
    }
    __syncthreads();

    // forward FFT realizes inverse: A -> B;  ifft(W) = conj(fft(conj(W)))/N
    fft3072_pp(Za, Zb, tid);

    // window + store both frames vectorized (read from B)
    const float inv = 1.0f/(float)WIN;
    float* scx = g_scratch + (b*NT + t0)*WIN;
    float* scy = scx + WIN;
    #pragma unroll
    for (int it = 0; it < WIN/(4*NTHREADS); it++){
        int n = 4*(tid + NTHREADS*it);
        float4 h4 = *(const float4*)&g_hann[n];
        float2 u0 = Zb[PHY(n+0)], u1 = Zb[PHY(n+1)], u2 = Zb[PHY(n+2)], u3 = Zb[PHY(n+3)];
        float4 xo = make_float4( u0.x*inv*h4.x,  u1.x*inv*h4.y,  u2.x*inv*h4.z,  u3.x*inv*h4.w);
        float4 yo = make_float4(-u0.y*inv*h4.x, -u1.y*inv*h4.y, -u2.y*inv*h4.z, -u3.y*inv*h4.w);
        *(float4*)&scx[n] = xo;
        *(float4*)&scy[n] = yo;
    }
}

// 4 consecutive outputs per thread; interior frames contribute aligned float4.
__global__ void ola_kernel(float* __restrict__ out){
    const int GP = NOISE_LEN/4;            // 47952 groups per batch
    int gid = blockIdx.x*blockDim.x + threadIdx.x;
    if (gid >= NB*GP) return;
    int b = gid / GP;
    int g = gid - b*GP;
    int s = 4*g + HALF;                    // s % 4 == 0
    const float* base = g_scratch + b*NT*WIN;

    int tl0 = (s     >= 2880) ? (s     - 2880)/HOP : 0;   // t_lo for element 0
    int tl3 = (s + 3 >= 2880) ? (s + 3 - 2880)/HOP : 0;   // t_lo for element 3
    int th0 = s/HOP;       if (th0 > NT-1) th0 = NT-1;    // t_hi for element 0
    int th3 = (s + 3)/HOP; if (th3 > NT-1) th3 = NT-1;    // t_hi for element 3

    float4 acc = make_float4(0.f, 0.f, 0.f, 0.f);
    for (int tt = tl3; tt <= th0; tt++){
        float4 vv = *(const float4*)&base[tt*WIN + (s - HOP*tt)];
        acc.x += vv.x; acc.y += vv.y; acc.z += vv.z; acc.w += vv.w;
    }
    for (int tt = tl0; tt < tl3; tt++){
        int o0 = s - HOP*tt;
        if (o0+0 <= WIN-1) acc.x += base[tt*WIN + o0+0];
        if (o0+1 <= WIN-1) acc.y += base[tt*WIN + o0+1];
        if (o0+2 <= WIN-1) acc.z += base[tt*WIN + o0+2];
        if (o0+3 <= WIN-1) acc.w += base[tt*WIN + o0+3];
    }
    for (int tt = th0+1; tt <= th3; tt++){
        int o0 = s - HOP*tt;
        if (o0+0 >= 0) acc.x += base[tt*WIN + o0+0];
        if (o0+1 >= 0) acc.y += base[tt*WIN + o0+1];
        if (o0+2 >= 0) acc.z += base[tt*WIN + o0+2];
        if (o0+3 >= 0) acc.w += base[tt*WIN + o0+3];
    }
    *(float4*)&out[b*NOISE_LEN + 4*g] = acc;
}

// ---------------------------------------------------------------- launch
extern "C" void kernel_launch(void* const* d_in, const int* in_sizes, int n_in,
                              void* d_out, int out_size){
    const float* fb    = (const float*)d_in[0];
    const float* noise = (const float*)d_in[1];
    if (n_in >= 2 && in_sizes[0] == NB*NOISE_LEN && in_sizes[1] == NB*NF*NT){
        const float* tmp = fb; fb = noise; noise = tmp;
    }
    float* out = (float*)d_out;

    cudaFuncSetAttribute(synth_kernel,
                         cudaFuncAttributeMaxDynamicSharedMemorySize, SMEM_BYTES);

    init_tables<<<(WIN + 255)/256, 256>>>();
    dim3 grid(NT/2, NB);
    synth_kernel<<<grid, NTHREADS, SMEM_BYTES>>>(fb, noise);
    int n_groups = NB*(NOISE_LEN/4);
    ola_kernel<<<(n_groups + 255)/256, 256>>>(out);
}

// round 9
// speedup vs baseline: 1.5177x; 1.1611x over previous
#include <cuda_runtime.h>

#define WIN   3072
#define HOP   192
#define NB    8
#define NT    1000
#define NF    128
#define NOISE_LEN ((NT-1)*HOP)   /* 191808 */
#define HALF  (WIN/2)            /* 1536 */
#define NTHREADS 256

#define PHY(i) ((i) + ((i)>>5))
#define SBUF (WIN + (WIN>>5))    /* 3168 */
#define SMEM_BYTES (2*SBUF*(int)sizeof(float2))   /* 50688 */

__device__ float2 g_tw[WIN];      // w3072^j = exp(-2*pi*i*j/3072)
__device__ float  g_hann[WIN];
__device__ float  g_scratch[NB*NT*WIN];   // windowed out_frames, ~98 MB

// ---------------------------------------------------------------- complex ops
__device__ __forceinline__ float2 cadd(float2 a, float2 b){ return make_float2(a.x+b.x, a.y+b.y); }
__device__ __forceinline__ float2 csub(float2 a, float2 b){ return make_float2(a.x-b.x, a.y-b.y); }
__device__ __forceinline__ float2 cmul(float2 a, float2 b){
    return make_float2(a.x*b.x - a.y*b.y, a.x*b.y + a.y*b.x);
}

// forward DFT-4 (e^{-2pi i jk/4})
__device__ __forceinline__ void dft4(float2 &a0, float2 &a1, float2 &a2, float2 &a3){
    float2 t0 = cadd(a0,a2), t1 = csub(a0,a2);
    float2 t2 = cadd(a1,a3), t3 = csub(a1,a3);
    a0 = cadd(t0,t2);
    a2 = csub(t0,t2);
    a1 = make_float2(t1.x + t3.y, t1.y - t3.x);  // t1 - i*t3
    a3 = make_float2(t1.x - t3.y, t1.y + t3.x);  // t1 + i*t3
}

// forward DFT-3
__device__ __forceinline__ void dft3(float2 &a, float2 &b, float2 &c){
    float2 s = cadd(b,c);
    float2 d = csub(b,c);
    float2 t = make_float2(a.x - 0.5f*s.x, a.y - 0.5f*s.y);
    float ux = 0.8660254037844386f*d.x, uy = 0.8660254037844386f*d.y;
    float2 y0 = cadd(a,s);
    b = make_float2(t.x + uy, t.y - ux);  // t - i*u
    c = make_float2(t.x - uy, t.y + ux);  // t + i*u
    a = y0;
}

// DFT-12, input v[j] with j = r + 4c. After: X[k3 + 3*k1] at v[k1 + 4*k3].
__device__ __forceinline__ void dft12(float2 *v){
    dft3(v[0], v[4], v[8]);
    dft3(v[1], v[5], v[9]);
    dft3(v[2], v[6], v[10]);
    dft3(v[3], v[7], v[11]);
    const float H3 = 0.8660254037844386f;
    v[5]  = cmul(v[5],  make_float2( H3,  -0.5f));   // w12^1
    v[6]  = cmul(v[6],  make_float2( 0.5f, -H3));    // w12^2
    v[7]  = make_float2(v[7].y, -v[7].x);            // w12^3 = -i
    v[9]  = cmul(v[9],  make_float2( 0.5f, -H3));    // w12^2
    v[10] = cmul(v[10], make_float2(-0.5f, -H3));    // w12^4
    v[11] = make_float2(-v[11].x, -v[11].y);         // w12^6 = -1
    dft4(v[0], v[1], v[2],  v[3]);
    dft4(v[4], v[5], v[6],  v[7]);
    dft4(v[8], v[9], v[10], v[11]);
}

// DFT-16, input v[j] with j = r + 4c. After: X[k4 + 4*k1] at v[k1 + 4*k4].
__device__ __forceinline__ void dft16(float2 *v){
    dft4(v[0], v[4], v[8],  v[12]);
    dft4(v[1], v[5], v[9],  v[13]);
    dft4(v[2], v[6], v[10], v[14]);
    dft4(v[3], v[7], v[11], v[15]);
    const float C1 = 0.9238795325112867f;
    const float S1 = 0.3826834323650898f;
    const float R2 = 0.7071067811865476f;
    v[5]  = cmul(v[5],  make_float2( C1, -S1));   // w16^1
    v[6]  = cmul(v[6],  make_float2( R2, -R2));   // w16^2
    v[7]  = cmul(v[7],  make_float2( S1, -C1));   // w16^3
    v[9]  = cmul(v[9],  make_float2( R2, -R2));   // w16^2
    v[10] = make_float2(v[10].y, -v[10].x);       // w16^4 = -i
    v[11] = cmul(v[11], make_float2(-R2, -R2));   // w16^6
    v[13] = cmul(v[13], make_float2( S1, -C1));   // w16^3
    v[14] = cmul(v[14], make_float2(-R2, -R2));   // w16^6
    v[15] = cmul(v[15], make_float2(-C1,  S1));   // w16^9
    dft4(v[0], v[1], v[2],  v[3]);
    dft4(v[4], v[5], v[6],  v[7]);
    dft4(v[8], v[9], v[10], v[11]);
    dft4(v[12],v[13],v[14], v[15]);
}

// radix-16 MIDDLE stage: src -> dst, 192 butterflies (tid = 12*p + q), twiddled
__device__ __forceinline__ void stage16_mid(const float2 *src, float2 *dst, int tid){
    if (tid < 192){
        float2 v[16];
        int q = tid % 12, p = tid / 12;
        #pragma unroll
        for (int i = 0; i < 16; i++) v[i] = src[PHY(tid + 192*i)];
        dft16(v);
        #pragma unroll
        for (int k = 0; k < 16; k++){
            float2 X = v[(k>>2) + 4*(k&3)];
            if (k && p) X = cmul(X, g_tw[12*p*k]);   // w256^{pk}
            dst[PHY(q + 192*p + 12*k)] = X;
        }
    }
    __syncthreads();
}

// radix-16 LAST stage: src -> dst, NO twiddle, output mapping tid + 192*k
__device__ __forceinline__ void stage16_last(const float2 *src, float2 *dst, int tid){
    if (tid < 192){
        float2 v[16];
        #pragma unroll
        for (int i = 0; i < 16; i++) v[i] = src[PHY(tid + 192*i)];
        dft16(v);
        #pragma unroll
        for (int k = 0; k < 16; k++){
            float2 X = v[(k>>2) + 4*(k&3)];
            dst[PHY(tid + 192*k)] = X;
        }
    }
    __syncthreads();
}

// ---------------------------------------------------------------- kernels
__global__ void init_tables(){
    int j = blockIdx.x*blockDim.x + threadIdx.x;
    if (j < WIN){
        float s, c;
        sincospif(-2.0f * (float)j / (float)WIN, &s, &c);
        g_tw[j] = make_float2(c, s);
        float sh = sinpif((float)j / (float)(WIN-1));
        g_hann[j] = sh * sh;   // 0.5 - 0.5*cos(2*pi*j/(N-1))
    }
}

// One block = one PAIR of frames (2t, 2t+1) packed as z = x + i*y.
// Fully fused: gmem->stage1, filter->stage1', stage3'->gmem. 6 barriers total.
__global__ void __launch_bounds__(NTHREADS, 3)
synth_kernel(const float* __restrict__ fb, const float* __restrict__ noise){
    extern __shared__ float2 smem2[];
    float2* Za = smem2;          // buffer A
    float2* Zb = smem2 + SBUF;   // buffer B
    __shared__ float gsx[NF];
    __shared__ float gsy[NF];

    int tp  = blockIdx.x;          // 0..499
    int b   = blockIdx.y;
    int tid = threadIdx.x;
    int t0  = 2*tp;

    // filter gains for frames t0, t0+1 (consumed after >=3 barriers: safe)
    if (tid < NF){
        float2 g2 = *(const float2*)&fb[(b*NF + tid)*NT + t0];
        gsx[tid] = g2.x;
        gsy[tid] = g2.y;
    }

    int base = t0*HOP - HALF;
    const float* nb = noise + b*NOISE_LEN;

    // ======== forward FFT: gmem -> s1 -> Zb -> s2(mid) -> Za -> s3(last) -> Zb
    {
        float2 v[12];
        int p = tid;
        #pragma unroll
        for (int i = 0; i < 12; i++){
            int n  = p + 256*i;
            int i0 = base + n;
            int i1 = i0 + HOP;
            float x = (i0 >= 0 && i0 < NOISE_LEN) ? __ldg(&nb[i0]) : 0.0f;
            float y = (i1 >= 0 && i1 < NOISE_LEN) ? __ldg(&nb[i1]) : 0.0f;
            v[i] = make_float2(x, y);
        }
        dft12(v);
        #pragma unroll
        for (int k = 0; k < 12; k++){
            float2 X = v[(k/3) + 4*(k%3)];
            if (k) X = cmul(X, g_tw[p*k]);
            Zb[PHY(12*p + k)] = X;
        }
        __syncthreads();
    }
    stage16_mid (Zb, Za, tid);   // s2 (twiddled)
    stage16_last(Za, Zb, tid);   // s3 (no twiddle): forward spectrum now in Zb

    // ======== inverse FFT with fused filter:
    //   s1' reads filtered spectrum directly from Zb, writes Za
    {
        float2 v[12];
        int p = tid;
        #pragma unroll
        for (int i = 0; i < 12; i++){
            int n = p + 256*i;
            float2 W;
            if (n == 0){
                W = make_float2(0.0f, 0.0f);                 // H[0] = 0
            } else if (n == HALF){
                float2 A = Zb[PHY(HALF)];                    // Nyquist (X,Y real)
                W = make_float2(gsx[NF-1]*A.x, -gsy[NF-1]*A.y);
            } else {
                int k    = (n < HALF) ? n : (WIN - n);       // 1..1535
                float2 A = Zb[PHY(k)];
                float2 B = Zb[PHY(WIN - k)];
                float Xx = 0.5f*(A.x + B.x), Xy = 0.5f*(A.y - B.y);
                float Yx = 0.5f*(A.y + B.y), Yy = -0.5f*(A.x - B.x);
                int band = (k - 1)/12;
                float hx = gsx[band], hy = gsy[band];
                if (n < HALF){
                    W = make_float2(hx*Xx - hy*Yy, -(hx*Xy + hy*Yx));
                } else {
                    W = make_float2(hx*Xx + hy*Yy, -(-hx*Xy + hy*Yx));
                }
            }
            v[i] = W;
        }
        dft12(v);
        #pragma unroll
        for (int k = 0; k < 12; k++){
            float2 X = v[(k/3) + 4*(k%3)];
            if (k) X = cmul(X, g_tw[p*k]);
            Za[PHY(12*p + k)] = X;
        }
        __syncthreads();
    }
    stage16_mid(Za, Zb, tid);   // s2' (twiddled)

    // s3' (last, no twiddle): Zb -> registers -> windowed, coalesced STG to scratch
    if (tid < 192){
        float2 v[16];
        #pragma unroll
        for (int i = 0; i < 16; i++) v[i] = Zb[PHY(tid + 192*i)];
        dft16(v);
        const float inv = 1.0f/(float)WIN;
        float* scx = g_scratch + (b*NT + t0)*WIN;
        float* scy = scx + WIN;
        #pragma unroll
        for (int k = 0; k < 16; k++){
            float2 X = v[(k>>2) + 4*(k&3)];
            int n = tid + 192*k;
            float w = inv * __ldg(&g_hann[n]);
            scx[n] =  X.x * w;    // frame t0   = Re(u)/N * hann
            scy[n] = -X.y * w;    // frame t0+1 = -Im(u)/N * hann
        }
    }
}

// 4 consecutive outputs per thread; interior frames contribute aligned float4.
__global__ void ola_kernel(float* __restrict__ out){
    const int GP = NOISE_LEN/4;            // 47952 groups per batch
    int gid = blockIdx.x*blockDim.x + threadIdx.x;
    if (gid >= NB*GP) return;
    int b = gid / GP;
    int g = gid - b*GP;
    int s = 4*g + HALF;                    // s % 4 == 0
    const float* base = g_scratch + b*NT*WIN;

    int tl0 = (s     >= 2880) ? (s     - 2880)/HOP : 0;   // t_lo for element 0
    int tl3 = (s + 3 >= 2880) ? (s + 3 - 2880)/HOP : 0;   // t_lo for element 3
    int th0 = s/HOP;       if (th0 > NT-1) th0 = NT-1;    // t_hi for element 0
    int th3 = (s + 3)/HOP; if (th3 > NT-1) th3 = NT-1;    // t_hi for element 3

    float4 acc = make_float4(0.f, 0.f, 0.f, 0.f);
    for (int tt = tl3; tt <= th0; tt++){
        float4 vv = *(const float4*)&base[tt*WIN + (s - HOP*tt)];
        acc.x += vv.x; acc.y += vv.y; acc.z += vv.z; acc.w += vv.w;
    }
    for (int tt = tl0; tt < tl3; tt++){
        int o0 = s - HOP*tt;
        if (o0+0 <= WIN-1) acc.x += base[tt*WIN + o0+0];
        if (o0+1 <= WIN-1) acc.y += base[tt*WIN + o0+1];
        if (o0+2 <= WIN-1) acc.z += base[tt*WIN + o0+2];
        if (o0+3 <= WIN-1) acc.w += base[tt*WIN + o0+3];
    }
    for (int tt = th0+1; tt <= th3; tt++){
        int o0 = s - HOP*tt;
        if (o0+0 >= 0) acc.x += base[tt*WIN + o0+0];
        if (o0+1 >= 0) acc.y += base[tt*WIN + o0+1];
        if (o0+2 >= 0) acc.z += base[tt*WIN + o0+2];
        if (o0+3 >= 0) acc.w += base[tt*WIN + o0+3];
    }
    *(float4*)&out[b*NOISE_LEN + 4*g] = acc;
}

// ---------------------------------------------------------------- launch
extern "C" void kernel_launch(void* const* d_in, const int* in_sizes, int n_in,
                              void* d_out, int out_size){
    const float* fb    = (const float*)d_in[0];
    const float* noise = (const float*)d_in[1];
    if (n_in >= 2 && in_sizes[0] == NB*NOISE_LEN && in_sizes[1] == NB*NF*NT){
        const float* tmp = fb; fb = noise; noise = tmp;
    }
    float* out = (float*)d_out;

    cudaFuncSetAttribute(synth_kernel,
                         cudaFuncAttributeMaxDynamicSharedMemorySize, SMEM_BYTES);

    init_tables<<<(WIN + 255)/256, 256>>>();
    dim3 grid(NT/2, NB);
    synth_kernel<<<grid, NTHREADS, SMEM_BYTES>>>(fb, noise);
    int n_groups = NB*(NOISE_LEN/4);
    ola_kernel<<<(n_groups + 255)/256, 256>>>(out);
}

// round 10
// speedup vs baseline: 1.6319x; 1.0752x over previous
#include <cuda_runtime.h>
#include <cuda_fp16.h>

#define WIN   3072
#define HOP   192
#define NB    8
#define NT    1000
#define NF    128
#define NOISE_LEN ((NT-1)*HOP)   /* 191808 */
#define HALF  (WIN/2)            /* 1536 */
#define NTHREADS 256

#define PHY(i) ((i) + ((i)>>5))
#define SBUF (WIN + (WIN>>5))    /* 3168 */
#define SMEM_BYTES (2*SBUF*(int)sizeof(float2))   /* 50688 */

__device__ float2 g_tw[WIN];      // w3072^j = exp(-2*pi*i*j/3072)
__device__ float  g_hann[WIN];
__device__ __half g_scratch[NB*NT*WIN];   // windowed out_frames, fp16, ~49 MB

// ---------------------------------------------------------------- complex ops
__device__ __forceinline__ float2 cadd(float2 a, float2 b){ return make_float2(a.x+b.x, a.y+b.y); }
__device__ __forceinline__ float2 csub(float2 a, float2 b){ return make_float2(a.x-b.x, a.y-b.y); }
__device__ __forceinline__ float2 cmul(float2 a, float2 b){
    return make_float2(a.x*b.x - a.y*b.y, a.x*b.y + a.y*b.x);
}

// forward DFT-4 (e^{-2pi i jk/4})
__device__ __forceinline__ void dft4(float2 &a0, float2 &a1, float2 &a2, float2 &a3){
    float2 t0 = cadd(a0,a2), t1 = csub(a0,a2);
    float2 t2 = cadd(a1,a3), t3 = csub(a1,a3);
    a0 = cadd(t0,t2);
    a2 = csub(t0,t2);
    a1 = make_float2(t1.x + t3.y, t1.y - t3.x);  // t1 - i*t3
    a3 = make_float2(t1.x - t3.y, t1.y + t3.x);  // t1 + i*t3
}

// forward DFT-3
__device__ __forceinline__ void dft3(float2 &a, float2 &b, float2 &c){
    float2 s = cadd(b,c);
    float2 d = csub(b,c);
    float2 t = make_float2(a.x - 0.5f*s.x, a.y - 0.5f*s.y);
    float ux = 0.8660254037844386f*d.x, uy = 0.8660254037844386f*d.y;
    float2 y0 = cadd(a,s);
    b = make_float2(t.x + uy, t.y - ux);  // t - i*u
    c = make_float2(t.x - uy, t.y + ux);  // t + i*u
    a = y0;
}

// DFT-12, input v[j] with j = r + 4c. After: X[k3 + 3*k1] at v[k1 + 4*k3].
__device__ __forceinline__ void dft12(float2 *v){
    dft3(v[0], v[4], v[8]);
    dft3(v[1], v[5], v[9]);
    dft3(v[2], v[6], v[10]);
    dft3(v[3], v[7], v[11]);
    const float H3 = 0.8660254037844386f;
    v[5]  = cmul(v[5],  make_float2( H3,  -0.5f));   // w12^1
    v[6]  = cmul(v[6],  make_float2( 0.5f, -H3));    // w12^2
    v[7]  = make_float2(v[7].y, -v[7].x);            // w12^3 = -i
    v[9]  = cmul(v[9],  make_float2( 0.5f, -H3));    // w12^2
    v[10] = cmul(v[10], make_float2(-0.5f, -H3));    // w12^4
    v[11] = make_float2(-v[11].x, -v[11].y);         // w12^6 = -1
    dft4(v[0], v[1], v[2],  v[3]);
    dft4(v[4], v[5], v[6],  v[7]);
    dft4(v[8], v[9], v[10], v[11]);
}

// DFT-16, input v[j] with j = r + 4c. After: X[k4 + 4*k1] at v[k1 + 4*k4].
__device__ __forceinline__ void dft16(float2 *v){
    dft4(v[0], v[4], v[8],  v[12]);
    dft4(v[1], v[5], v[9],  v[13]);
    dft4(v[2], v[6], v[10], v[14]);
    dft4(v[3], v[7], v[11], v[15]);
    const float C1 = 0.9238795325112867f;
    const float S1 = 0.3826834323650898f;
    const float R2 = 0.7071067811865476f;
    v[5]  = cmul(v[5],  make_float2( C1, -S1));   // w16^1
    v[6]  = cmul(v[6],  make_float2( R2, -R2));   // w16^2
    v[7]  = cmul(v[7],  make_float2( S1, -C1));   // w16^3
    v[9]  = cmul(v[9],  make_float2( R2, -R2));   // w16^2
    v[10] = make_float2(v[10].y, -v[10].x);       // w16^4 = -i
    v[11] = cmul(v[11], make_float2(-R2, -R2));   // w16^6
    v[13] = cmul(v[13], make_float2( S1, -C1));   // w16^3
    v[14] = cmul(v[14], make_float2(-R2, -R2));   // w16^6
    v[15] = cmul(v[15], make_float2(-C1,  S1));   // w16^9
    dft4(v[0], v[1], v[2],  v[3]);
    dft4(v[4], v[5], v[6],  v[7]);
    dft4(v[8], v[9], v[10], v[11]);
    dft4(v[12],v[13],v[14], v[15]);
}

// radix-16 MIDDLE stage: src -> dst, 192 butterflies (tid = 12*p + q), twiddled
__device__ __forceinline__ void stage16_mid(const float2 *src, float2 *dst, int tid){
    if (tid < 192){
        float2 v[16];
        int q = tid % 12, p = tid / 12;
        #pragma unroll
        for (int i = 0; i < 16; i++) v[i] = src[PHY(tid + 192*i)];
        dft16(v);
        #pragma unroll
        for (int k = 0; k < 16; k++){
            float2 X = v[(k>>2) + 4*(k&3)];
            if (k && p) X = cmul(X, g_tw[12*p*k]);   // w256^{pk}
            dst[PHY(q + 192*p + 12*k)] = X;
        }
    }
    __syncthreads();
}

// radix-16 LAST stage: src -> dst, NO twiddle, output mapping tid + 192*k
__device__ __forceinline__ void stage16_last(const float2 *src, float2 *dst, int tid){
    if (tid < 192){
        float2 v[16];
        #pragma unroll
        for (int i = 0; i < 16; i++) v[i] = src[PHY(tid + 192*i)];
        dft16(v);
        #pragma unroll
        for (int k = 0; k < 16; k++){
            float2 X = v[(k>>2) + 4*(k&3)];
            dst[PHY(tid + 192*k)] = X;
        }
    }
    __syncthreads();
}

// ---------------------------------------------------------------- kernels
__global__ void init_tables(){
    int j = blockIdx.x*blockDim.x + threadIdx.x;
    if (j < WIN){
        float s, c;
        sincospif(-2.0f * (float)j / (float)WIN, &s, &c);
        g_tw[j] = make_float2(c, s);
        float sh = sinpif((float)j / (float)(WIN-1));
        g_hann[j] = sh * sh;   // 0.5 - 0.5*cos(2*pi*j/(N-1))
    }
}

// One block = one PAIR of frames (2t, 2t+1) packed as z = x + i*y.
// Fully fused: gmem->stage1, filter->stage1', stage3'->gmem(fp16). 6 barriers.
__global__ void __launch_bounds__(NTHREADS, 3)
synth_kernel(const float* __restrict__ fb, const float* __restrict__ noise){
    extern __shared__ float2 smem2[];
    float2* Za = smem2;          // buffer A
    float2* Zb = smem2 + SBUF;   // buffer B
    __shared__ float gsx[NF];
    __shared__ float gsy[NF];

    int tp  = blockIdx.x;          // 0..499
    int b   = blockIdx.y;
    int tid = threadIdx.x;
    int t0  = 2*tp;

    // filter gains for frames t0, t0+1 (consumed after >=3 barriers: safe)
    if (tid < NF){
        float2 g2 = *(const float2*)&fb[(b*NF + tid)*NT + t0];
        gsx[tid] = g2.x;
        gsy[tid] = g2.y;
    }

    int base = t0*HOP - HALF;
    const float* nb = noise + b*NOISE_LEN;

    // ======== forward FFT: gmem -> s1 -> Zb -> s2(mid) -> Za -> s3(last) -> Zb
    {
        float2 v[12];
        int p = tid;
        #pragma unroll
        for (int i = 0; i < 12; i++){
            int n  = p + 256*i;
            int i0 = base + n;
            int i1 = i0 + HOP;
            float x = (i0 >= 0 && i0 < NOISE_LEN) ? __ldg(&nb[i0]) : 0.0f;
            float y = (i1 >= 0 && i1 < NOISE_LEN) ? __ldg(&nb[i1]) : 0.0f;
            v[i] = make_float2(x, y);
        }
        dft12(v);
        #pragma unroll
        for (int k = 0; k < 12; k++){
            float2 X = v[(k/3) + 4*(k%3)];
            if (k) X = cmul(X, g_tw[p*k]);
            Zb[PHY(12*p + k)] = X;
        }
        __syncthreads();
    }
    stage16_mid (Zb, Za, tid);   // s2 (twiddled)
    stage16_last(Za, Zb, tid);   // s3 (no twiddle): forward spectrum now in Zb

    // ======== inverse FFT with fused filter:
    //   s1' reads filtered spectrum directly from Zb, writes Za
    {
        float2 v[12];
        int p = tid;
        #pragma unroll
        for (int i = 0; i < 12; i++){
            int n = p + 256*i;
            float2 W;
            if (n == 0){
                W = make_float2(0.0f, 0.0f);                 // H[0] = 0
            } else if (n == HALF){
                float2 A = Zb[PHY(HALF)];                    // Nyquist (X,Y real)
                W = make_float2(gsx[NF-1]*A.x, -gsy[NF-1]*A.y);
            } else {
                int k    = (n < HALF) ? n : (WIN - n);       // 1..1535
                float2 A = Zb[PHY(k)];
                float2 B = Zb[PHY(WIN - k)];
                float Xx = 0.5f*(A.x + B.x), Xy = 0.5f*(A.y - B.y);
                float Yx = 0.5f*(A.y + B.y), Yy = -0.5f*(A.x - B.x);
                int band = (k - 1)/12;
                float hx = gsx[band], hy = gsy[band];
                if (n < HALF){
                    W = make_float2(hx*Xx - hy*Yy, -(hx*Xy + hy*Yx));
                } else {
                    W = make_float2(hx*Xx + hy*Yy, -(-hx*Xy + hy*Yx));
                }
            }
            v[i] = W;
        }
        dft12(v);
        #pragma unroll
        for (int k = 0; k < 12; k++){
            float2 X = v[(k/3) + 4*(k%3)];
            if (k) X = cmul(X, g_tw[p*k]);
            Za[PHY(12*p + k)] = X;
        }
        __syncthreads();
    }
    stage16_mid(Za, Zb, tid);   // s2' (twiddled)

    // s3' (last): Zb -> registers -> windowed, coalesced fp16 STG to scratch
    if (tid < 192){
        float2 v[16];
        #pragma unroll
        for (int i = 0; i < 16; i++) v[i] = Zb[PHY(tid + 192*i)];
        dft16(v);
        const float inv = 1.0f/(float)WIN;
        __half* scx = g_scratch + (size_t)(b*NT + t0)*WIN;
        __half* scy = scx + WIN;
        #pragma unroll
        for (int k = 0; k < 16; k++){
            float2 X = v[(k>>2) + 4*(k&3)];
            int n = tid + 192*k;
            float w = inv * __ldg(&g_hann[n]);
            scx[n] = __float2half_rn( X.x * w);   // frame t0
            scy[n] = __float2half_rn(-X.y * w);   // frame t0+1
        }
    }
}

// 4 consecutive outputs per thread; interior frames contribute one aligned
// 8-byte load (4 halfs).
__global__ void ola_kernel(float* __restrict__ out){
    const int GP = NOISE_LEN/4;            // 47952 groups per batch
    int gid = blockIdx.x*blockDim.x + threadIdx.x;
    if (gid >= NB*GP) return;
    int b = gid / GP;
    int g = gid - b*GP;
    int s = 4*g + HALF;                    // s % 4 == 0
    const __half* base = g_scratch + (size_t)b*NT*WIN;

    int tl0 = (s     >= 2880) ? (s     - 2880)/HOP : 0;   // t_lo for element 0
    int tl3 = (s + 3 >= 2880) ? (s + 3 - 2880)/HOP : 0;   // t_lo for element 3
    int th0 = s/HOP;       if (th0 > NT-1) th0 = NT-1;    // t_hi for element 0
    int th3 = (s + 3)/HOP; if (th3 > NT-1) th3 = NT-1;    // t_hi for element 3

    float4 acc = make_float4(0.f, 0.f, 0.f, 0.f);
    // frames valid for all 4 elements: one 8-byte load (offset is mult of 4 halfs)
    for (int tt = tl3; tt <= th0; tt++){
        const __half2* p2 = (const __half2*)&base[tt*WIN + (s - HOP*tt)];
        float2 lo = __half22float2(p2[0]);
        float2 hi = __half22float2(p2[1]);
        acc.x += lo.x; acc.y += lo.y; acc.z += hi.x; acc.w += hi.y;
    }
    for (int tt = tl0; tt < tl3; tt++){
        int o0 = s - HOP*tt;
        if (o0+0 <= WIN-1) acc.x += __half2float(base[tt*WIN + o0+0]);
        if (o0+1 <= WIN-1) acc.y += __half2float(base[tt*WIN + o0+1]);
        if (o0+2 <= WIN-1) acc.z += __half2float(base[tt*WIN + o0+2]);
        if (o0+3 <= WIN-1) acc.w += __half2float(base[tt*WIN + o0+3]);
    }
    for (int tt = th0+1; tt <= th3; tt++){
        int o0 = s - HOP*tt;
        if (o0+0 >= 0) acc.x += __half2float(base[tt*WIN + o0+0]);
        if (o0+1 >= 0) acc.y += __half2float(base[tt*WIN + o0+1]);
        if (o0+2 >= 0) acc.z += __half2float(base[tt*WIN + o0+2]);
        if (o0+3 >= 0) acc.w += __half2float(base[tt*WIN + o0+3]);
    }
    *(float4*)&out[b*NOISE_LEN + 4*g] = acc;
}

// ---------------------------------------------------------------- launch
extern "C" void kernel_launch(void* const* d_in, const int* in_sizes, int n_in,
                              void* d_out, int out_size){
    const float* fb    = (const float*)d_in[0];
    const float* noise = (const float*)d_in[1];
    if (n_in >= 2 && in_sizes[0] == NB*NOISE_LEN && in_sizes[1] == NB*NF*NT){
        const float* tmp = fb; fb = noise; noise = tmp;
    }
    float* out = (float*)d_out;

    cudaFuncSetAttribute(synth_kernel,
                         cudaFuncAttributeMaxDynamicSharedMemorySize, SMEM_BYTES);

    init_tables<<<(WIN + 255)/256, 256>>>();
    dim3 grid(NT/2, NB);
    synth_kernel<<<grid, NTHREADS, SMEM_BYTES>>>(fb, noise);
    int n_groups = NB*(NOISE_LEN/4);
    ola_kernel<<<(n_groups + 255)/256, 256>>>(out);
}